// round 8
// baseline (speedup 1.0000x reference)
#include <cuda_runtime.h>
#include <cstdint>
#include <cstddef>

#define Bn   32
#define Tn   2048
#define XD   64
#define ZD   128
#define Hh   512
#define TAUc 16
#define DD   192   // XD + ZD

// ---------------- device scratch (no allocations allowed) ----------------
__device__ float g_v[XD * TAUc * DD];                 // v[i][k][d]
__device__ float g_c[XD * TAUc];                      // c[i][k]
__device__ float g_vxT2[2 * TAUc * 32 * 64];          // [ihalf][k][d2][il*2+p]
__device__ float g_VzP[(TAUc + 1) * XD * ZD];         // prefix sums of vz over k
__device__ float g_cP[(TAUc + 1) * XD];               // prefix sums of c  over k

typedef unsigned long long u64;

__device__ __forceinline__ void fma2(u64& d, u64 a, u64 b) {
    // packed 2x fp32 FMA (sm_100+): d = a*b + d, elementwise on packed f32x2
    asm("fma.rn.f32x2 %0, %1, %2, %0;" : "+l"(d) : "l"(a), "l"(b));
}

// ---------------------------------------------------------------------------
// Kernel 1: fused W1 transpose-copy (-> influence_matrices) + v = W1@W2 + c.
// One block per (i,k) slab: reads/writes contiguous 192x512 floats, coalesced
// float4 both ways; W1 is read exactly ONCE for both outputs.
// ---------------------------------------------------------------------------
__global__ void __launch_bounds__(256) k_prep(
    const float* __restrict__ W1, const float* __restrict__ b1,
    const float* __restrict__ W2, const float* __restrict__ b2,
    float* __restrict__ IM)
{
    int blk = blockIdx.x;             // blk = i*16 + k
    int i = blk >> 4, k = blk & 15;
    const float* w1 = W1 + (size_t)blk * (DD * Hh);
    float*       im = IM + (size_t)(k * XD + i) * (DD * Hh);

    __shared__ float w2s[Hh];
    __shared__ float cred[8];
    int tid = threadIdx.x;

    for (int h = tid; h < Hh; h += 256) w2s[h] = W2[(size_t)blk * Hh + h];
    __syncthreads();

    // c[i][k] = dot(b1[i,k,:], W2[i,k,:]) + b2[i,k]
    float cp = 0.f;
    for (int h = tid; h < Hh; h += 256) cp += b1[(size_t)blk * Hh + h] * w2s[h];
    #pragma unroll
    for (int o = 16; o; o >>= 1) cp += __shfl_down_sync(0xffffffffu, cp, o);
    if ((tid & 31) == 0) cred[tid >> 5] = cp;
    __syncthreads();
    if (tid == 0) {
        float s = 0.f;
        #pragma unroll
        for (int w = 0; w < 8; w++) s += cred[w];
        g_c[blk] = s + b2[blk];
    }

    // transpose-copy + per-row dot with W2
    int warp = tid >> 5, lane = tid & 31;
    for (int d = warp; d < DD; d += 8) {
        const float4* src = (const float4*)(w1 + (size_t)d * Hh);
        float4*       dst = (float4*)(im + (size_t)d * Hh);
        const float4* w24 = (const float4*)w2s;
        float acc = 0.f;
        #pragma unroll
        for (int c4 = 0; c4 < 4; c4++) {
            float4 v4 = src[lane + c4 * 32];
            dst[lane + c4 * 32] = v4;
            float4 w4 = w24[lane + c4 * 32];
            acc += v4.x * w4.x + v4.y * w4.y + v4.z * w4.z + v4.w * w4.w;
        }
        #pragma unroll
        for (int o = 16; o; o >>= 1) acc += __shfl_down_sync(0xffffffffu, acc, o);
        if (lane == 0) g_v[(size_t)blk * DD + d] = acc;
    }
}

// ---------------------------------------------------------------------------
// Kernel 1b: prefix sums over k (for t<16 masking) + repack vx into the
// interleaved d-pair layout the conv kernel loads as LDS.64.
// ---------------------------------------------------------------------------
__global__ void __launch_bounds__(128) k_prefix()
{
    int i = blockIdx.x, t = threadIdx.x;

    if (t < ZD) {                     // vz prefix sums along k (d' = t)
        float s = 0.f;
        g_VzP[(size_t)(0 * XD + i) * ZD + t] = 0.f;
        for (int m = 1; m <= TAUc; m++) {
            s += g_v[((size_t)i * TAUc + (m - 1)) * DD + XD + t];
            g_VzP[((size_t)m * XD + i) * ZD + t] = s;
        }
    }
    if (t == 0) {                     // c prefix sums
        float cs = 0.f;
        g_cP[0 * XD + i] = 0.f;
        for (int m = 1; m <= TAUc; m++) {
            cs += g_c[i * TAUc + m - 1];
            g_cP[m * XD + i] = cs;
        }
    }
    // vx repack: g_vxT2[bz][k][d2][il*2+p] = v[i][k][2*d2+p], i = bz*32+il
    int bz = i >> 5, il = i & 31;
    for (int e = t; e < TAUc * XD; e += 128) {
        int k = e >> 6, d = e & 63;
        int d2 = d >> 1, p = d & 1;
        g_vxT2[(size_t)bz * (TAUc * 32 * 64) + (size_t)((k * 32 + d2) * 64) + il * 2 + p] =
            g_v[((size_t)i * TAUc + k) * DD + d];
    }
}

// ---------------------------------------------------------------------------
// Kernel 2: causal 16-tap, 64-channel convolution via packed f32x2 FMA.
// ---------------------------------------------------------------------------
#define CONV_SMEM (TAUc * 32 * 64 * 4 + 144 * 64 * 4)   // 131072 + 36864 B

__global__ void __launch_bounds__(256, 1) k_conv(
    const float* __restrict__ x, float* __restrict__ out)
{
    extern __shared__ float sm[];
    float* vx_sh = sm;                     // 32768 floats: [(k*32+d2)*64 + il*2 + p]
    float* x_sh  = sm + TAUc * 32 * 64;    // 9216 floats:  [r*64 + d], r=0..143

    int tt = blockIdx.x, b = blockIdx.y, bz = blockIdx.z;
    int t0 = tt * 128;
    int tid = threadIdx.x;

    const float* vsrc = g_vxT2 + (size_t)bz * (TAUc * 32 * 64);
    for (int e = tid; e < TAUc * 32 * 64; e += 256) vx_sh[e] = vsrc[e];

    const float* xb = x + (size_t)b * Tn * XD;
    for (int e = tid; e < 144 * 64; e += 256) {
        int r = e >> 6;
        int t = t0 - 16 + r;
        x_sh[e] = (t >= 0) ? xb[(size_t)t * XD + (e & 63)] : 0.f;
    }
    __syncthreads();

    int il = tid & 31, tg = tid >> 5;
    int tbase = tg * 16;                   // local t offset within the 128-tile

    u64 acc2[16];
    #pragma unroll
    for (int j = 0; j < 16; j++) acc2[j] = 0ull;

    const float* xr0 = x_sh + tbase * 64;  // row r=tbase <=> x index (t0+tbase-16)
    for (int d2 = 0; d2 < 32; d2++) {
        u64 xw[31];
        #pragma unroll
        for (int m = 0; m < 31; m++)
            xw[m] = *(const u64*)(xr0 + m * 64 + 2 * d2);   // (x[.,2d2], x[.,2d2+1])
        u64 vv[16];
        #pragma unroll
        for (int k = 0; k < 16; k++)
            vv[k] = *(const u64*)(vx_sh + (k * 32 + d2) * 64 + il * 2);
        #pragma unroll
        for (int j = 0; j < 16; j++)
            #pragma unroll
            for (int k = 0; k < 16; k++)
                fma2(acc2[j], xw[15 + j - k], vv[k]);        // x[t-1-k] * vx[i,k]
    }

    float* ob = out + ((size_t)b * Tn + t0 + tbase) * XD + bz * 32 + il;
    #pragma unroll
    for (int j = 0; j < 16; j++) {
        unsigned lo, hi;
        asm("mov.b64 {%0,%1}, %2;" : "=r"(lo), "=r"(hi) : "l"(acc2[j]));
        ob[(size_t)j * XD] = __uint_as_float(lo) + __uint_as_float(hi);  // even-d + odd-d halves
    }
}

// ---------------------------------------------------------------------------
// Kernel 3 (NEW): out += z . VzP[16] + cP[16] as a register-tiled f32x2 GEMM.
// Block = 128 t x 64 i, thread micro-tile = 4 t x 8 i.
// Per d2 iter: 4 broadcast LDS.64 (z) + 8 conflict-free LDS.64 (vz) + 32 FFMA2.
// z smem rows padded to 65 u64 so the 4 distinct per-warp t-rows hit
// distinct banks (row stride 520 words = 8 mod 32).
// t<16 rows get corrected by k_fix afterwards.
// ---------------------------------------------------------------------------
#define ZB2_SMEM (128 * 65 * 8 + 64 * 64 * 8 + 64 * 4)   // 66560 + 32768 + 256

__global__ void __launch_bounds__(256) k_zbias2(
    const float* __restrict__ z, float* __restrict__ out)
{
    extern __shared__ char smraw[];
    u64*   z2  = (u64*)smraw;                      // [t][65]  pair over z-d
    u64*   vz2 = (u64*)(smraw + 128 * 65 * 8);     // [d2][i]  pair over z-d
    float* cps = (float*)(smraw + 128 * 65 * 8 + 64 * 64 * 8);  // cP[16][i]

    int tt = blockIdx.x, b = blockIdx.y;
    int t0 = tt * 128;
    int tid = threadIdx.x;

    // load z tile [128 t][128 d] as u64 pairs, padded rows
    const u64* zb = (const u64*)(z + ((size_t)b * Tn + t0) * ZD);
    for (int e = tid; e < 128 * 64; e += 256) {
        int t = e >> 6, d2 = e & 63;
        z2[t * 65 + d2] = zb[e];
    }
    // load VzP[16] for all 64 i, layout [d2][i]
    const u64* vsrc = (const u64*)(g_VzP + (size_t)TAUc * XD * ZD);
    for (int e = tid; e < 64 * 64; e += 256) {
        int i = e >> 6, d2 = e & 63;
        vz2[d2 * 64 + i] = vsrc[(size_t)i * 64 + d2];
    }
    if (tid < 64) cps[tid] = g_cP[TAUc * XD + tid];
    __syncthreads();

    int ig = tid & 7;          // i group: owns i = ig + 8r, r=0..7
    int tg = tid >> 3;         // t group: owns t_loc = tg*4 + j, j=0..3
    int tl0 = tg * 4;

    u64 acc2[4][8];
    #pragma unroll
    for (int j = 0; j < 4; j++)
        #pragma unroll
        for (int r = 0; r < 8; r++) acc2[j][r] = 0ull;

    for (int d2 = 0; d2 < 64; d2++) {
        u64 zw[4];
        #pragma unroll
        for (int j = 0; j < 4; j++) zw[j] = z2[(tl0 + j) * 65 + d2];
        u64 vv[8];
        #pragma unroll
        for (int r = 0; r < 8; r++) vv[r] = vz2[d2 * 64 + ig + 8 * r];
        #pragma unroll
        for (int j = 0; j < 4; j++)
            #pragma unroll
            for (int r = 0; r < 8; r++)
                fma2(acc2[j][r], zw[j], vv[r]);
    }

    float* ob = out + ((size_t)b * Tn + t0 + tl0) * XD;
    #pragma unroll
    for (int j = 0; j < 4; j++)
        #pragma unroll
        for (int r = 0; r < 8; r++) {
            unsigned lo, hi;
            asm("mov.b64 {%0,%1}, %2;" : "=r"(lo), "=r"(hi) : "l"(acc2[j][r]));
            int i = ig + 8 * r;
            float add = __uint_as_float(lo) + __uint_as_float(hi) + cps[i];
            ob[(size_t)j * XD + i] += add;
        }
}

// ---------------------------------------------------------------------------
// Kernel 4: fixup for t < 16 (masked taps): the main pass applied VzP[16]/cP[16]
// everywhere; correct rows t=0..15 with z.(VzP[t]-VzP[16]) + (cP[t]-cP[16]).
// Tiny: 32 blocks x 1024 outputs x 128-d dot, all L2-resident.
// ---------------------------------------------------------------------------
__global__ void __launch_bounds__(256) k_fix(
    const float* __restrict__ z, float* __restrict__ out)
{
    int b = blockIdx.x;
    for (int it = 0; it < 4; it++) {
        int idx = threadIdx.x + it * 256;      // 1024 = 16 t x 64 i
        int t = idx >> 6, i = idx & 63;
        const float* zr   = z + ((size_t)b * Tn + t) * ZD;
        const float* vz_t = g_VzP + ((size_t)t * XD + i) * ZD;
        const float* vz_f = g_VzP + ((size_t)TAUc * XD + i) * ZD;
        float a = g_cP[t * XD + i] - g_cP[TAUc * XD + i];
        for (int d = 0; d < ZD; d++)
            a += zr[d] * (vz_t[d] - vz_f[d]);
        out[((size_t)b * Tn + t) * XD + i] += a;
    }
}

// ---------------------------------------------------------------------------
extern "C" void kernel_launch(void* const* d_in, const int* in_sizes, int n_in,
                              void* d_out, int out_size)
{
    const float* z  = (const float*)d_in[0];
    const float* x  = (const float*)d_in[1];
    const float* W1 = (const float*)d_in[2];
    const float* b1 = (const float*)d_in[3];
    const float* W2 = (const float*)d_in[4];
    const float* b2 = (const float*)d_in[5];

    float* out = (float*)d_out;                       // [B,T,XD] float32
    float* IM  = out + (size_t)Bn * Tn * XD;          // [TAU,XD,DD,H] float32

    cudaFuncSetAttribute(k_conv,   cudaFuncAttributeMaxDynamicSharedMemorySize, CONV_SMEM);
    cudaFuncSetAttribute(k_zbias2, cudaFuncAttributeMaxDynamicSharedMemorySize, ZB2_SMEM);

    k_prep<<<XD * TAUc, 256>>>(W1, b1, W2, b2, IM);
    k_prefix<<<XD, 128>>>();
    k_conv<<<dim3(Tn / 128, Bn, 2), 256, CONV_SMEM>>>(x, out);
    k_zbias2<<<dim3(Tn / 128, Bn), 256, ZB2_SMEM>>>(z, out);
    k_fix<<<Bn, 256>>>(z, out);
}

// round 11
// speedup vs baseline: 1.3493x; 1.3493x over previous
#include <cuda_runtime.h>
#include <cstdint>
#include <cstddef>

#define Bn   32
#define Tn   2048
#define XD   64
#define ZD   128
#define Hh   512
#define TAUc 16
#define DD   192   // XD + ZD

typedef unsigned long long u64;

// ---------------- device scratch (no allocations allowed) ----------------
__device__ float g_v[XD * TAUc * DD];                 // v[i][k][d]
__device__ float g_c[XD * TAUc];                      // c[i][k]
__device__ float g_vxT2[2 * TAUc * 32 * 64];          // [ihalf][k][d2][il*2+p]
__device__ float g_VzP16[XD * ZD];                    // full-tap vz sum, [i][d]
__device__ u64   g_VzPT[TAUc * 64 * XD];              // [t][d2][i] paired over d
__device__ float g_cP[(TAUc + 1) * XD];               // prefix sums of c over k

__device__ __forceinline__ void fma2(u64& d, u64 a, u64 b) {
    // packed 2x fp32 FMA (sm_100+): d = a*b + d, elementwise on packed f32x2
    asm("fma.rn.f32x2 %0, %1, %2, %0;" : "+l"(d) : "l"(a), "l"(b));
}

// ---------------------------------------------------------------------------
// Kernel 1: fused W1 transpose-copy (-> influence_matrices) + v = W1@W2 + c.
// One block per (i,k) slab; 2-row unroll -> 8 independent LDG.128 in flight.
// ---------------------------------------------------------------------------
__global__ void __launch_bounds__(256) k_prep(
    const float* __restrict__ W1, const float* __restrict__ b1,
    const float* __restrict__ W2, const float* __restrict__ b2,
    float* __restrict__ IM)
{
    int blk = blockIdx.x;             // blk = i*16 + k
    int i = blk >> 4, k = blk & 15;
    const float* w1 = W1 + (size_t)blk * (DD * Hh);
    float*       im = IM + (size_t)(k * XD + i) * (DD * Hh);

    __shared__ float w2s[Hh];
    __shared__ float cred[8];
    int tid = threadIdx.x;

    for (int h = tid; h < Hh; h += 256) w2s[h] = W2[(size_t)blk * Hh + h];
    __syncthreads();

    // c[i][k] = dot(b1[i,k,:], W2[i,k,:]) + b2[i,k]
    float cp = 0.f;
    for (int h = tid; h < Hh; h += 256) cp += b1[(size_t)blk * Hh + h] * w2s[h];
    #pragma unroll
    for (int o = 16; o; o >>= 1) cp += __shfl_down_sync(0xffffffffu, cp, o);
    if ((tid & 31) == 0) cred[tid >> 5] = cp;
    __syncthreads();
    if (tid == 0) {
        float s = 0.f;
        #pragma unroll
        for (int w = 0; w < 8; w++) s += cred[w];
        g_c[blk] = s + b2[blk];
    }

    // transpose-copy + per-row dot with W2, two rows per iteration
    int warp = tid >> 5, lane = tid & 31;
    const float4* w24 = (const float4*)w2s;
    for (int d = warp; d < DD; d += 16) {
        const float4* srcA = (const float4*)(w1 + (size_t)d * Hh);
        const float4* srcB = (const float4*)(w1 + (size_t)(d + 8) * Hh);
        float4*       dstA = (float4*)(im + (size_t)d * Hh);
        float4*       dstB = (float4*)(im + (size_t)(d + 8) * Hh);
        float accA = 0.f, accB = 0.f;
        #pragma unroll
        for (int c4 = 0; c4 < 4; c4++) {
            float4 a4 = srcA[lane + c4 * 32];
            float4 b4 = srcB[lane + c4 * 32];
            dstA[lane + c4 * 32] = a4;
            dstB[lane + c4 * 32] = b4;
            float4 w4 = w24[lane + c4 * 32];
            accA += a4.x * w4.x + a4.y * w4.y + a4.z * w4.z + a4.w * w4.w;
            accB += b4.x * w4.x + b4.y * w4.y + b4.z * w4.z + b4.w * w4.w;
        }
        #pragma unroll
        for (int o = 16; o; o >>= 1) {
            accA += __shfl_down_sync(0xffffffffu, accA, o);
            accB += __shfl_down_sync(0xffffffffu, accB, o);
        }
        if (lane == 0) {
            g_v[(size_t)blk * DD + d]     = accA;
            g_v[(size_t)blk * DD + d + 8] = accB;
        }
    }
}

// ---------------------------------------------------------------------------
// Kernel 1b: per-i prefix sums over k (staged in smem), emit:
//   g_VzP16[i][d]      full 16-tap vz sum   (zbias main pass)
//   g_VzPT[t][d2][i]   paired/transposed VzP[t] for t<16 (coalesced fixup)
//   g_cP               c prefix sums
//   g_vxT2             interleaved vx layout for conv
// ---------------------------------------------------------------------------
__global__ void __launch_bounds__(128) k_prefix()
{
    __shared__ float P[TAUc + 1][ZD];
    int i = blockIdx.x, t = threadIdx.x;

    float s = 0.f;
    P[0][t] = 0.f;
    #pragma unroll
    for (int m = 1; m <= TAUc; m++) {
        s += g_v[((size_t)i * TAUc + (m - 1)) * DD + XD + t];
        P[m][t] = s;
    }
    g_VzP16[(size_t)i * ZD + t] = s;

    if (t == 0) {
        float cs = 0.f;
        g_cP[0 * XD + i] = 0.f;
        #pragma unroll
        for (int m = 1; m <= TAUc; m++) {
            cs += g_c[i * TAUc + m - 1];
            g_cP[m * XD + i] = cs;
        }
    }
    __syncthreads();

    // transposed paired layout for the t<16 fixup
    for (int e = t; e < TAUc * 64; e += 128) {
        int tt = e >> 6, d2 = e & 63;
        float lo = P[tt][2 * d2], hi = P[tt][2 * d2 + 1];
        u64 pk;
        asm("mov.b64 %0, {%1,%2};" : "=l"(pk)
            : "r"(__float_as_uint(lo)), "r"(__float_as_uint(hi)));
        g_VzPT[(size_t)(tt * 64 + d2) * XD + i] = pk;
    }

    // vx repack: g_vxT2[bz][k][d2][il*2+p] = v[i][k][2*d2+p], i = bz*32+il
    int bz = i >> 5, il = i & 31;
    for (int e = t; e < TAUc * XD; e += 128) {
        int k = e >> 6, d = e & 63;
        int d2 = d >> 1, p = d & 1;
        g_vxT2[(size_t)bz * (TAUc * 32 * 64) + (size_t)((k * 32 + d2) * 64) + il * 2 + p] =
            g_v[((size_t)i * TAUc + k) * DD + d];
    }
}

// ---------------------------------------------------------------------------
// Kernel 2: z-projection + bias, register-tiled f32x2 GEMM. WRITES out.
// Block = 128 t x 64 i, thread micro-tile 4 t x 8 i. tt==0 blocks also
// handle the t<16 masked rows via coalesced g_VzPT loads.
// ---------------------------------------------------------------------------
#define ZB2_SMEM (128 * 65 * 8 + 64 * 64 * 8 + 64 * 4)   // 66560 + 32768 + 256

__global__ void __launch_bounds__(256) k_zbias2(
    const float* __restrict__ z, float* __restrict__ out)
{
    extern __shared__ char smraw[];
    u64*   z2  = (u64*)smraw;                      // [t][65]  pair over z-d
    u64*   vz2 = (u64*)(smraw + 128 * 65 * 8);     // [d2][i]  pair over z-d
    float* cps = (float*)(smraw + 128 * 65 * 8 + 64 * 64 * 8);  // cP[16][i]

    int tt = blockIdx.x, b = blockIdx.y;
    int t0 = tt * 128;
    int tid = threadIdx.x;

    const u64* zb = (const u64*)(z + ((size_t)b * Tn + t0) * ZD);
    for (int e = tid; e < 128 * 64; e += 256) {
        int t = e >> 6, d2 = e & 63;
        z2[t * 65 + d2] = zb[e];
    }
    const u64* vsrc = (const u64*)g_VzP16;         // [i][64] u64
    for (int e = tid; e < 64 * 64; e += 256) {
        int i = e >> 6, d2 = e & 63;
        vz2[d2 * 64 + i] = vsrc[(size_t)i * 64 + d2];
    }
    if (tid < 64) cps[tid] = g_cP[TAUc * XD + tid];
    __syncthreads();

    int ig = tid & 7;          // i group: owns i = ig + 8r
    int tg = tid >> 3;         // t group: owns t_loc = tg*4 + j
    int tl0 = tg * 4;

    u64 acc2[4][8];
    #pragma unroll
    for (int j = 0; j < 4; j++)
        #pragma unroll
        for (int r = 0; r < 8; r++) acc2[j][r] = 0ull;

    for (int d2 = 0; d2 < 64; d2++) {
        u64 zw[4];
        #pragma unroll
        for (int j = 0; j < 4; j++) zw[j] = z2[(tl0 + j) * 65 + d2];
        u64 vv[8];
        #pragma unroll
        for (int r = 0; r < 8; r++) vv[r] = vz2[d2 * 64 + ig + 8 * r];
        #pragma unroll
        for (int j = 0; j < 4; j++)
            #pragma unroll
            for (int r = 0; r < 8; r++)
                fma2(acc2[j][r], zw[j], vv[r]);
    }

    bool fixblock = (tt == 0);
    float* ob = out + ((size_t)b * Tn + t0 + tl0) * XD;
    #pragma unroll
    for (int j = 0; j < 4; j++) {
        if (fixblock && (tl0 + j) < 16) continue;   // masked rows done below
        #pragma unroll
        for (int r = 0; r < 8; r++) {
            unsigned lo, hi;
            asm("mov.b64 {%0,%1}, %2;" : "=r"(lo), "=r"(hi) : "l"(acc2[j][r]));
            int i = ig + 8 * r;
            ob[(size_t)j * XD + i] = __uint_as_float(lo) + __uint_as_float(hi) + cps[i];
        }
    }

    if (fixblock) {
        // rows t=0..15: out = z . VzP[t] + cP[t], VzPT loads lane-coalesced
        #pragma unroll
        for (int c = 0; c < 4; c++) {
            int idx = c * 256 + tid;
            int t = idx >> 6, i = idx & 63;
            u64 a = 0ull;
            const u64* vp = g_VzPT + (size_t)(t * 64) * XD + i;
            for (int d2 = 0; d2 < 64; d2++)
                fma2(a, z2[t * 65 + d2], vp[(size_t)d2 * XD]);
            unsigned lo, hi;
            asm("mov.b64 {%0,%1}, %2;" : "=r"(lo), "=r"(hi) : "l"(a));
            out[((size_t)b * Tn + t) * XD + i] =
                __uint_as_float(lo) + __uint_as_float(hi) + g_cP[t * XD + i];
        }
    }
}

// ---------------------------------------------------------------------------
// Kernel 3: causal 16-tap, 64-channel convolution via packed f32x2 FMA.
// ACCUMULATES into out (zbias wrote the z+bias part first).
// ---------------------------------------------------------------------------
#define CONV_SMEM (TAUc * 32 * 64 * 4 + 144 * 64 * 4)   // 131072 + 36864 B

__global__ void __launch_bounds__(256, 1) k_conv(
    const float* __restrict__ x, float* __restrict__ out)
{
    extern __shared__ float sm[];
    float* vx_sh = sm;                     // 32768 floats: [(k*32+d2)*64 + il*2 + p]
    float* x_sh  = sm + TAUc * 32 * 64;    // 9216 floats:  [r*64 + d], r=0..143

    int tt = blockIdx.x, b = blockIdx.y, bz = blockIdx.z;
    int t0 = tt * 128;
    int tid = threadIdx.x;

    const float* vsrc = g_vxT2 + (size_t)bz * (TAUc * 32 * 64);
    for (int e = tid; e < TAUc * 32 * 64; e += 256) vx_sh[e] = vsrc[e];

    const float* xb = x + (size_t)b * Tn * XD;
    for (int e = tid; e < 144 * 64; e += 256) {
        int r = e >> 6;
        int t = t0 - 16 + r;
        x_sh[e] = (t >= 0) ? xb[(size_t)t * XD + (e & 63)] : 0.f;
    }
    __syncthreads();

    int il = tid & 31, tg = tid >> 5;
    int tbase = tg * 16;                   // local t offset within the 128-tile

    u64 acc2[16];
    #pragma unroll
    for (int j = 0; j < 16; j++) acc2[j] = 0ull;

    const float* xr0 = x_sh + tbase * 64;  // row r=tbase <=> x index (t0+tbase-16)
    for (int d2 = 0; d2 < 32; d2++) {
        u64 xw[31];
        #pragma unroll
        for (int m = 0; m < 31; m++)
            xw[m] = *(const u64*)(xr0 + m * 64 + 2 * d2);   // (x[.,2d2], x[.,2d2+1])
        u64 vv[16];
        #pragma unroll
        for (int k = 0; k < 16; k++)
            vv[k] = *(const u64*)(vx_sh + (k * 32 + d2) * 64 + il * 2);
        #pragma unroll
        for (int j = 0; j < 16; j++)
            #pragma unroll
            for (int k = 0; k < 16; k++)
                fma2(acc2[j], xw[15 + j - k], vv[k]);        // x[t-1-k] * vx[i,k]
    }

    float* ob = out + ((size_t)b * Tn + t0 + tbase) * XD + bz * 32 + il;
    #pragma unroll
    for (int j = 0; j < 16; j++) {
        unsigned lo, hi;
        asm("mov.b64 {%0,%1}, %2;" : "=r"(lo), "=r"(hi) : "l"(acc2[j]));
        ob[(size_t)j * XD] += __uint_as_float(lo) + __uint_as_float(hi);
    }
}

// ---------------------------------------------------------------------------
extern "C" void kernel_launch(void* const* d_in, const int* in_sizes, int n_in,
                              void* d_out, int out_size)
{
    const float* z  = (const float*)d_in[0];
    const float* x  = (const float*)d_in[1];
    const float* W1 = (const float*)d_in[2];
    const float* b1 = (const float*)d_in[3];
    const float* W2 = (const float*)d_in[4];
    const float* b2 = (const float*)d_in[5];

    float* out = (float*)d_out;                       // [B,T,XD] float32
    float* IM  = out + (size_t)Bn * Tn * XD;          // [TAU,XD,DD,H] float32

    cudaFuncSetAttribute(k_conv,   cudaFuncAttributeMaxDynamicSharedMemorySize, CONV_SMEM);
    cudaFuncSetAttribute(k_zbias2, cudaFuncAttributeMaxDynamicSharedMemorySize, ZB2_SMEM);

    k_prep<<<XD * TAUc, 256>>>(W1, b1, W2, b2, IM);
    k_prefix<<<XD, 128>>>();
    k_zbias2<<<dim3(Tn / 128, Bn), 256, ZB2_SMEM>>>(z, out);      // writes out
    k_conv<<<dim3(Tn / 128, Bn, 2), 256, CONV_SMEM>>>(x, out);    // += conv
}